// round 1
// baseline (speedup 1.0000x reference)
#include <cuda_runtime.h>
#include <cuda_bf16.h>
#include <float.h>
#include <math.h>

// Problem shape (fixed by reference setup_inputs)
#define B_   16
#define C_   256
#define H_   128
#define W_   128
#define HW_  (H_ * W_)           // 16384
#define HW4_ (HW_ / 4)           // 4096 float4 columns per image

// Scratch: feat [B, 2, H, W]  (avg then max), 2 MiB floats = 8 MB
__device__ float g_feat[B_ * 2 * HW_];

// ---------------------------------------------------------------------------
// Kernel 1: channel-wise mean + max over C=256.
// One thread per float4 spatial chunk. Loads are coalesced across the warp
// (consecutive hw) and strided by HW*4 bytes across the c loop.
// ---------------------------------------------------------------------------
__global__ __launch_bounds__(256) void reduce_mean_max_kernel(
    const float* __restrict__ x)
{
    const int idx = blockIdx.x * blockDim.x + threadIdx.x;  // 0 .. B*HW4-1
    const int b   = idx >> 12;         // / HW4_ (4096)
    const int hw4 = idx & (HW4_ - 1);

    const float4* xb = reinterpret_cast<const float4*>(x)
                     + (size_t)b * C_ * HW4_ + hw4;

    float4 s = make_float4(0.f, 0.f, 0.f, 0.f);
    float4 m = make_float4(-FLT_MAX, -FLT_MAX, -FLT_MAX, -FLT_MAX);

    #pragma unroll 8
    for (int c = 0; c < C_; ++c) {
        float4 v = __ldcs(xb + (size_t)c * HW4_);
        s.x += v.x; s.y += v.y; s.z += v.z; s.w += v.w;
        m.x = fmaxf(m.x, v.x); m.y = fmaxf(m.y, v.y);
        m.z = fmaxf(m.z, v.z); m.w = fmaxf(m.w, v.w);
    }

    const float inv = 1.0f / (float)C_;
    float4 a = make_float4(s.x * inv, s.y * inv, s.z * inv, s.w * inv);

    float4* fa = reinterpret_cast<float4*>(g_feat) + (size_t)b * 2 * HW4_ + hw4;
    fa[0]    = a;   // channel 0: avg
    fa[HW4_] = m;   // channel 1: max
}

// ---------------------------------------------------------------------------
// Kernel 2: 3x3 conv (2 in ch, 1 out ch, pad 1, no bias) + sigmoid.
// One thread per output pixel. feat is 2 MiB -> L2 resident.
// ---------------------------------------------------------------------------
__global__ __launch_bounds__(256) void conv_sigmoid_kernel(
    const float* __restrict__ conv_w,   // [1,2,3,3] OIHW
    float* __restrict__ out)            // [B,1,H,W]
{
    const int idx = blockIdx.x * blockDim.x + threadIdx.x;  // 0 .. B*HW-1
    const int b  = idx >> 14;           // / HW_
    const int hw = idx & (HW_ - 1);
    const int h  = hw >> 7;             // / W_
    const int w  = hw & (W_ - 1);

    // weights: broadcast reads, served by L1/L2 constant-like caching
    float wk[18];
    #pragma unroll
    for (int i = 0; i < 18; ++i) wk[i] = __ldg(conv_w + i);

    const float* f0 = g_feat + (size_t)b * 2 * HW_;   // avg channel
    const float* f1 = f0 + HW_;                       // max channel

    float acc = 0.f;
    #pragma unroll
    for (int kh = 0; kh < 3; ++kh) {
        const int hh = h + kh - 1;
        if (hh < 0 || hh >= H_) continue;
        #pragma unroll
        for (int kw = 0; kw < 3; ++kw) {
            const int ww = w + kw - 1;
            if (ww < 0 || ww >= W_) continue;
            const int off = hh * W_ + ww;
            acc = fmaf(f0[off], wk[kh * 3 + kw], acc);
            acc = fmaf(f1[off], wk[9 + kh * 3 + kw], acc);
        }
    }

    out[idx] = 1.0f / (1.0f + __expf(-acc));
}

// ---------------------------------------------------------------------------
extern "C" void kernel_launch(void* const* d_in, const int* in_sizes, int n_in,
                              void* d_out, int out_size)
{
    const float* x      = (const float*)d_in[0];   // [16,256,128,128] f32
    const float* conv_w = (const float*)d_in[1];   // [1,2,3,3] f32
    float*       out    = (float*)d_out;           // [16,1,128,128] f32

    // Kernel 1: B*HW4 = 65536 threads
    reduce_mean_max_kernel<<<(B_ * HW4_) / 256, 256>>>(x);

    // Kernel 2: B*HW = 262144 threads
    conv_sigmoid_kernel<<<(B_ * HW_) / 256, 256>>>(conv_w, out);
}

// round 2
// speedup vs baseline: 1.0780x; 1.0780x over previous
#include <cuda_runtime.h>
#include <cuda_bf16.h>
#include <float.h>
#include <math.h>

// Problem shape (fixed by reference setup_inputs)
#define B_   16
#define C_   256
#define H_   128
#define W_   128
#define HW_  (H_ * W_)           // 16384
#define HW4_ (HW_ / 4)           // 4096 float4 columns per image
#define W4_  (W_ / 4)            // 32

// Scratch: feat [B, 2, H, W]  (avg then max)
__device__ float g_feat[B_ * 2 * HW_];

// ---------------------------------------------------------------------------
// Kernel 1: channel-wise mean + max over C=256.
// Block = 256 threads = (64 hw4-columns) x (4 channel-splits).
// Each thread streams 64 channels of one float4 column; smem combines the 4
// channel-splits. Grid = 1024 blocks -> fine-grained SM load balance.
// ---------------------------------------------------------------------------
__global__ __launch_bounds__(256) void reduce_mean_max_kernel(
    const float* __restrict__ x)
{
    __shared__ float4 s_sum[256];
    __shared__ float4 s_max[256];

    const int local = threadIdx.x & 63;       // hw4 within block
    const int cs    = threadIdx.x >> 6;       // channel split 0..3

    const int blk   = blockIdx.x;             // 0..1023
    const int b     = blk >> 6;                      // / 64
    const int hw4   = ((blk & 63) << 6) + local;     // 64 columns per block

    const float4* xb = reinterpret_cast<const float4*>(x)
                     + (size_t)b * C_ * HW4_ + (size_t)(cs * 64) * HW4_ + hw4;

    float4 s = make_float4(0.f, 0.f, 0.f, 0.f);
    float4 m = make_float4(-FLT_MAX, -FLT_MAX, -FLT_MAX, -FLT_MAX);

    #pragma unroll 8
    for (int c = 0; c < 64; ++c) {
        float4 v = __ldcs(xb + (size_t)c * HW4_);
        s.x += v.x; s.y += v.y; s.z += v.z; s.w += v.w;
        m.x = fmaxf(m.x, v.x); m.y = fmaxf(m.y, v.y);
        m.z = fmaxf(m.z, v.z); m.w = fmaxf(m.w, v.w);
    }

    s_sum[threadIdx.x] = s;
    s_max[threadIdx.x] = m;
    __syncthreads();

    if (threadIdx.x < 64) {
        #pragma unroll
        for (int k = 1; k < 4; ++k) {
            float4 ps = s_sum[threadIdx.x + k * 64];
            float4 pm = s_max[threadIdx.x + k * 64];
            s.x += ps.x; s.y += ps.y; s.z += ps.z; s.w += ps.w;
            m.x = fmaxf(m.x, pm.x); m.y = fmaxf(m.y, pm.y);
            m.z = fmaxf(m.z, pm.z); m.w = fmaxf(m.w, pm.w);
        }
        const float inv = 1.0f / (float)C_;
        float4 a = make_float4(s.x * inv, s.y * inv, s.z * inv, s.w * inv);

        float4* fa = reinterpret_cast<float4*>(g_feat)
                   + (size_t)b * 2 * HW4_ + hw4;
        fa[0]    = a;   // channel 0: avg
        fa[HW4_] = m;   // channel 1: max
    }
}

// ---------------------------------------------------------------------------
// Kernel 2: 3x3 conv (2 in ch, 1 out ch, pad 1, no bias) + sigmoid.
// One thread per 4 output pixels (float4 along W). Row loads amortized.
// ---------------------------------------------------------------------------
__global__ __launch_bounds__(256) void conv_sigmoid_kernel(
    const float* __restrict__ conv_w,   // [1,2,3,3] OIHW
    float* __restrict__ out)            // [B,1,H,W]
{
    const int idx = blockIdx.x * blockDim.x + threadIdx.x;  // 0 .. B*HW4-1
    const int b   = idx >> 12;            // / HW4_
    const int hw4 = idx & (HW4_ - 1);
    const int h   = hw4 >> 5;             // / W4_
    const int w0  = (hw4 & (W4_ - 1)) << 2;

    float wk[18];
    #pragma unroll
    for (int i = 0; i < 18; ++i) wk[i] = __ldg(conv_w + i);

    const float* f = g_feat + (size_t)b * 2 * HW_;

    float a0 = 0.f, a1 = 0.f, a2 = 0.f, a3 = 0.f;

    #pragma unroll
    for (int ch = 0; ch < 2; ++ch) {
        const float* fc = f + ch * HW_;
        #pragma unroll
        for (int r = 0; r < 3; ++r) {
            const int hh = h + r - 1;
            if (hh < 0 || hh >= H_) continue;
            const float* row = fc + hh * W_ + w0;
            float4 v = *reinterpret_cast<const float4*>(row);
            float  l = (w0 > 0)        ? row[-1] : 0.f;
            float  rr = (w0 + 4 < W_)  ? row[4]  : 0.f;

            const float k0 = wk[ch * 9 + r * 3 + 0];
            const float k1 = wk[ch * 9 + r * 3 + 1];
            const float k2 = wk[ch * 9 + r * 3 + 2];

            a0 = fmaf(l,   k0, fmaf(v.x, k1, fmaf(v.y, k2, a0)));
            a1 = fmaf(v.x, k0, fmaf(v.y, k1, fmaf(v.z, k2, a1)));
            a2 = fmaf(v.y, k0, fmaf(v.z, k1, fmaf(v.w, k2, a2)));
            a3 = fmaf(v.z, k0, fmaf(v.w, k1, fmaf(rr,  k2, a3)));
        }
    }

    float4 o;
    o.x = 1.0f / (1.0f + __expf(-a0));
    o.y = 1.0f / (1.0f + __expf(-a1));
    o.z = 1.0f / (1.0f + __expf(-a2));
    o.w = 1.0f / (1.0f + __expf(-a3));
    reinterpret_cast<float4*>(out)[idx] = o;
}

// ---------------------------------------------------------------------------
extern "C" void kernel_launch(void* const* d_in, const int* in_sizes, int n_in,
                              void* d_out, int out_size)
{
    const float* x      = (const float*)d_in[0];   // [16,256,128,128] f32
    const float* conv_w = (const float*)d_in[1];   // [1,2,3,3] f32
    float*       out    = (float*)d_out;           // [16,1,128,128] f32

    // Kernel 1: 1024 blocks x 256 threads
    reduce_mean_max_kernel<<<(B_ * HW4_) / 64, 256>>>(x);

    // Kernel 2: B*HW4 = 65536 threads -> 256 blocks
    conv_sigmoid_kernel<<<(B_ * HW4_) / 256, 256>>>(conv_w, out);
}

// round 3
// speedup vs baseline: 1.1700x; 1.0853x over previous
#include <cuda_runtime.h>
#include <cuda_bf16.h>
#include <float.h>
#include <math.h>

// Problem shape (fixed by reference setup_inputs)
#define B_   16
#define C_   256
#define H_   128
#define W_   128
#define HW_  (H_ * W_)           // 16384
#define HW4_ (HW_ / 4)           // 4096 float4 columns per image
#define W4_  (W_ / 4)            // 32

// Scratch: feat [B, 2, H, W]  (avg then max)
__device__ float g_feat[B_ * 2 * HW_];

// ---------------------------------------------------------------------------
// Kernel 1: channel-wise mean + max over C=256.
// Block = 256 threads = (32 hw4-columns) x (8 channel-splits of 32 channels).
// Grid = 2048 blocks (~1.7 waves) -> wave-2 work-stealing smooths the
// between-SM L2-die variance that capped R2 at 5.7 TB/s.
// ---------------------------------------------------------------------------
__global__ __launch_bounds__(256) void reduce_mean_max_kernel(
    const float* __restrict__ x)
{
    __shared__ float4 s_sum[256];
    __shared__ float4 s_max[256];

    const int col = threadIdx.x & 31;          // hw4 column within block
    const int cs  = threadIdx.x >> 5;          // channel split 0..7

    const int blk = blockIdx.x;                // 0..2047
    const int b   = blk >> 7;                  // / 128 tiles per image
    const int hw4 = ((blk & 127) << 5) + col;  // 32 columns per block

    const float4* xb = reinterpret_cast<const float4*>(x)
                     + (size_t)b * C_ * HW4_ + (size_t)(cs * 32) * HW4_ + hw4;

    float4 s = make_float4(0.f, 0.f, 0.f, 0.f);
    float4 m = make_float4(-FLT_MAX, -FLT_MAX, -FLT_MAX, -FLT_MAX);

    #pragma unroll 8
    for (int c = 0; c < 32; ++c) {
        float4 v = __ldcs(xb + (size_t)c * HW4_);
        s.x += v.x; s.y += v.y; s.z += v.z; s.w += v.w;
        m.x = fmaxf(m.x, v.x); m.y = fmaxf(m.y, v.y);
        m.z = fmaxf(m.z, v.z); m.w = fmaxf(m.w, v.w);
    }

    s_sum[threadIdx.x] = s;
    s_max[threadIdx.x] = m;
    __syncthreads();

    if (threadIdx.x < 32) {
        #pragma unroll
        for (int k = 1; k < 8; ++k) {
            float4 ps = s_sum[threadIdx.x + k * 32];
            float4 pm = s_max[threadIdx.x + k * 32];
            s.x += ps.x; s.y += ps.y; s.z += ps.z; s.w += ps.w;
            m.x = fmaxf(m.x, pm.x); m.y = fmaxf(m.y, pm.y);
            m.z = fmaxf(m.z, pm.z); m.w = fmaxf(m.w, pm.w);
        }
        const float inv = 1.0f / (float)C_;
        float4 a = make_float4(s.x * inv, s.y * inv, s.z * inv, s.w * inv);

        float4* fa = reinterpret_cast<float4*>(g_feat)
                   + (size_t)b * 2 * HW4_ + hw4;
        fa[0]    = a;   // channel 0: avg
        fa[HW4_] = m;   // channel 1: max
    }

    // Allow the PDL-dependent conv kernel to proceed as early as possible.
    __syncthreads();
    cudaTriggerProgrammaticLaunchCompletion();
}

// ---------------------------------------------------------------------------
// Kernel 2: 3x3 conv (2 in ch, 1 out ch, pad 1, no bias) + sigmoid.
// One thread per 4 output pixels (float4 along W). PDL: launched early,
// waits on kernel 1 via grid dependency sync.
// ---------------------------------------------------------------------------
__global__ __launch_bounds__(128) void conv_sigmoid_kernel(
    const float* __restrict__ conv_w,   // [1,2,3,3] OIHW
    float* __restrict__ out)            // [B,1,H,W]
{
    cudaGridDependencySynchronize();

    const int idx = blockIdx.x * blockDim.x + threadIdx.x;  // 0 .. B*HW4-1
    const int b   = idx >> 12;            // / HW4_
    const int hw4 = idx & (HW4_ - 1);
    const int h   = hw4 >> 5;             // / W4_
    const int w0  = (hw4 & (W4_ - 1)) << 2;

    float wk[18];
    #pragma unroll
    for (int i = 0; i < 18; ++i) wk[i] = __ldg(conv_w + i);

    const float* f = g_feat + (size_t)b * 2 * HW_;

    float a0 = 0.f, a1 = 0.f, a2 = 0.f, a3 = 0.f;

    #pragma unroll
    for (int ch = 0; ch < 2; ++ch) {
        const float* fc = f + ch * HW_;
        #pragma unroll
        for (int r = 0; r < 3; ++r) {
            const int hh = h + r - 1;
            if (hh < 0 || hh >= H_) continue;
            const float* row = fc + hh * W_ + w0;
            float4 v = *reinterpret_cast<const float4*>(row);
            float  l  = (w0 > 0)       ? row[-1] : 0.f;
            float  rr = (w0 + 4 < W_)  ? row[4]  : 0.f;

            const float k0 = wk[ch * 9 + r * 3 + 0];
            const float k1 = wk[ch * 9 + r * 3 + 1];
            const float k2 = wk[ch * 9 + r * 3 + 2];

            a0 = fmaf(l,   k0, fmaf(v.x, k1, fmaf(v.y, k2, a0)));
            a1 = fmaf(v.x, k0, fmaf(v.y, k1, fmaf(v.z, k2, a1)));
            a2 = fmaf(v.y, k0, fmaf(v.z, k1, fmaf(v.w, k2, a2)));
            a3 = fmaf(v.z, k0, fmaf(v.w, k1, fmaf(rr,  k2, a3)));
        }
    }

    float4 o;
    o.x = 1.0f / (1.0f + __expf(-a0));
    o.y = 1.0f / (1.0f + __expf(-a1));
    o.z = 1.0f / (1.0f + __expf(-a2));
    o.w = 1.0f / (1.0f + __expf(-a3));
    reinterpret_cast<float4*>(out)[idx] = o;
}

// ---------------------------------------------------------------------------
extern "C" void kernel_launch(void* const* d_in, const int* in_sizes, int n_in,
                              void* d_out, int out_size)
{
    const float* x      = (const float*)d_in[0];   // [16,256,128,128] f32
    const float* conv_w = (const float*)d_in[1];   // [1,2,3,3] f32
    float*       out    = (float*)d_out;           // [16,1,128,128] f32

    // Kernel 1: 2048 blocks x 256 threads
    reduce_mean_max_kernel<<<2048, 256>>>(x);

    // Kernel 2: 512 blocks x 128 threads, PDL-overlapped with kernel 1 drain
    cudaLaunchConfig_t cfg = {};
    cfg.gridDim  = dim3((B_ * HW4_) / 128, 1, 1);
    cfg.blockDim = dim3(128, 1, 1);
    cfg.dynamicSmemBytes = 0;
    cfg.stream = 0;

    cudaLaunchAttribute attrs[1];
    attrs[0].id = cudaLaunchAttributeProgrammaticStreamSerialization;
    attrs[0].val.programmaticStreamSerializationAllowed = 1;
    cfg.attrs = attrs;
    cfg.numAttrs = 1;

    cudaLaunchKernelEx(&cfg, conv_sigmoid_kernel, conv_w, out);
}